// round 1
// baseline (speedup 1.0000x reference)
#include <cuda_runtime.h>

// Problem constants (from reference): B=128, S=256, D=1024, BETA=1.0
#define BB 128
#define SS 256
#define DD 1024
#define BETA_F 1.0f

#define SPLIT 4            // blocks per batch
#define WARPS 8            // warps per block
#define NBLOCKS (BB * SPLIT)

__device__ float g_partials[NBLOCKS];

__global__ __launch_bounds__(WARPS * 32, 2)
void bridge_loss_kernel(const float* __restrict__ bridges,
                        const int*   __restrict__ b_inx,
                        const int*   __restrict__ neg_i,
                        const int*   __restrict__ neg_j)
{
    const int b    = blockIdx.x / SPLIT;
    const int part = blockIdx.x % SPLIT;
    const int warp = threadIdx.x >> 5;
    const int lane = threadIdx.x & 31;
    const int wib  = part * WARPS + warp;          // warp index within batch: 0..31

    // head / tail rows for this batch, cached in registers (reused ~8 rows/warp)
    const float4* base = (const float4*)(bridges + (size_t)b * SS * DD);
    const float4* hp   = base;                               // s = 0
    const float4* tp4  = base + (size_t)(SS - 1) * (DD / 4); // s = S-1

    float4 h[8], tl[8];
#pragma unroll
    for (int j = 0; j < 8; j++) {
        h[j]  = hp [lane + j * 32];
        tl[j] = tp4[lane + j * 32];
    }

    const float th = (float)b_inx[b * SS];
    const float tt = (float)b_inx[b * SS + SS - 1];
    const float inv_den = 1.0f / (tt - th);

    float wloss = 0.0f;

    for (int r = wib; r < SS - 2; r += SPLIT * WARPS) {
        const int s = r + 1;
        const float tpv   = (float)b_inx[b * SS + s];
        const float alpha = (tpv - th) * inv_den;
        const float sigma = alpha * (tt - tpv);
        const float inv   = 1.0f / (2.0f * sigma * sigma);

        const int ni = neg_i[b * (SS - 2) + r];
        const int nj = neg_j[b * (SS - 2) + r];

        const float4* pp = (const float4*)(bridges + ((size_t)b  * SS + s ) * DD);
        const float4* np = (const float4*)(bridges + ((size_t)ni * SS + nj) * DD);

        float acc = 0.0f;   // sum over d of (xn^2 - xp^2)
#pragma unroll
        for (int half = 0; half < 2; half++) {
            float4 p[4], n[4];
#pragma unroll
            for (int j = 0; j < 4; j++) {
                const int idx = lane + (half * 4 + j) * 32;
                p[j] = pp[idx];
                n[j] = np[idx];
            }
#pragma unroll
            for (int j = 0; j < 4; j++) {
                const int jj = half * 4 + j;
                const float4 hv = h[jj], tv = tl[jj], pv = p[j], nv = n[j];
                const float mx = fmaf(alpha, tv.x - hv.x, hv.x);
                const float my = fmaf(alpha, tv.y - hv.y, hv.y);
                const float mz = fmaf(alpha, tv.z - hv.z, hv.z);
                const float mw = fmaf(alpha, tv.w - hv.w, hv.w);
                const float xpx = pv.x - mx, xpy = pv.y - my, xpz = pv.z - mz, xpw = pv.w - mw;
                const float xnx = nv.x - mx, xny = nv.y - my, xnz = nv.z - mz, xnw = nv.w - mw;
                acc = fmaf(xnx, xnx, acc); acc = fmaf(-xpx, xpx, acc);
                acc = fmaf(xny, xny, acc); acc = fmaf(-xpy, xpy, acc);
                acc = fmaf(xnz, xnz, acc); acc = fmaf(-xpz, xpz, acc);
                acc = fmaf(xnw, xnw, acc); acc = fmaf(-xpw, xpw, acc);
            }
        }

        // warp tree reduce (all lanes end with the full sum)
#pragma unroll
        for (int off = 16; off; off >>= 1)
            acc += __shfl_xor_sync(0xffffffffu, acc, off);

        const float cur = fmaf(acc, inv, BETA_F);
        if (cur > 0.0f) wloss += cur;
    }

    __shared__ float sm[WARPS];
    if (lane == 0) sm[warp] = wloss;
    __syncthreads();
    if (threadIdx.x == 0) {
        float t = 0.0f;
#pragma unroll
        for (int w = 0; w < WARPS; w++) t += sm[w];
        g_partials[blockIdx.x] = t;
    }
}

__global__ void bridge_loss_reduce(float* __restrict__ out)
{
    __shared__ float sm[NBLOCKS];
    sm[threadIdx.x] = g_partials[threadIdx.x];
    __syncthreads();
#pragma unroll
    for (int st = NBLOCKS / 2; st > 0; st >>= 1) {
        if ((int)threadIdx.x < st) sm[threadIdx.x] += sm[threadIdx.x + st];
        __syncthreads();
    }
    if (threadIdx.x == 0) out[0] = sm[0] / (float)BB;
}

extern "C" void kernel_launch(void* const* d_in, const int* in_sizes, int n_in,
                              void* d_out, int out_size)
{
    const float* bridges = (const float*)d_in[0];
    const int*   b_inx   = (const int*)  d_in[1];
    const int*   neg_i   = (const int*)  d_in[2];
    const int*   neg_j   = (const int*)  d_in[3];

    bridge_loss_kernel<<<NBLOCKS, WARPS * 32>>>(bridges, b_inx, neg_i, neg_j);
    bridge_loss_reduce<<<1, NBLOCKS>>>((float*)d_out);
}

// round 2
// speedup vs baseline: 1.0062x; 1.0062x over previous
#include <cuda_runtime.h>

// Problem constants (from reference): B=128, S=256, D=1024, BETA=1.0
#define BB 128
#define SS 256
#define DD 1024
#define BETA_F 1.0f

#define SPLIT 4            // blocks per batch
#define WARPS 8            // warps per block
#define NBLOCKS (BB * SPLIT)
#define NTHREADS (WARPS * 32)

__device__ float g_partials[NBLOCKS];
__device__ unsigned g_ctr = 0;   // self-resetting via atomicInc wraparound

__global__ __launch_bounds__(NTHREADS, 2)
void bridge_loss_fused(const float* __restrict__ bridges,
                       const int*   __restrict__ b_inx,
                       const int*   __restrict__ neg_i,
                       const int*   __restrict__ neg_j,
                       float*       __restrict__ out)
{
    const int b    = blockIdx.x / SPLIT;
    const int part = blockIdx.x % SPLIT;
    const int warp = threadIdx.x >> 5;
    const int lane = threadIdx.x & 31;
    const int wib  = part * WARPS + warp;          // warp index within batch: 0..31

    // head / tail rows for this batch, cached in registers (reused ~8 rows/warp)
    const float4* base = (const float4*)(bridges + (size_t)b * SS * DD);
    const float4* hp   = base;                               // s = 0
    const float4* tp4  = base + (size_t)(SS - 1) * (DD / 4); // s = S-1

    float4 h[8], tl[8];
#pragma unroll
    for (int j = 0; j < 8; j++) {
        h[j]  = hp [lane + j * 32];
        tl[j] = tp4[lane + j * 32];
    }

    const float th = (float)b_inx[b * SS];
    const float tt = (float)b_inx[b * SS + SS - 1];
    const float inv_den = 1.0f / (tt - th);

    float wloss = 0.0f;

    for (int r = wib; r < SS - 2; r += SPLIT * WARPS) {
        const int s = r + 1;
        const float tpv   = (float)b_inx[b * SS + s];
        const float alpha = (tpv - th) * inv_den;
        const float sigma = alpha * (tt - tpv);
        const float inv   = 1.0f / (2.0f * sigma * sigma);

        const int ni = neg_i[b * (SS - 2) + r];
        const int nj = neg_j[b * (SS - 2) + r];

        const float4* pp = (const float4*)(bridges + ((size_t)b  * SS + s ) * DD);
        const float4* np = (const float4*)(bridges + ((size_t)ni * SS + nj) * DD);

        float acc = 0.0f;   // sum over d of (xn^2 - xp^2)
#pragma unroll
        for (int half = 0; half < 2; half++) {
            float4 p[4], n[4];
#pragma unroll
            for (int j = 0; j < 4; j++) {
                const int idx = lane + (half * 4 + j) * 32;
                p[j] = pp[idx];
                n[j] = np[idx];
            }
#pragma unroll
            for (int j = 0; j < 4; j++) {
                const int jj = half * 4 + j;
                const float4 hv = h[jj], tv = tl[jj], pv = p[j], nv = n[j];
                const float mx = fmaf(alpha, tv.x - hv.x, hv.x);
                const float my = fmaf(alpha, tv.y - hv.y, hv.y);
                const float mz = fmaf(alpha, tv.z - hv.z, hv.z);
                const float mw = fmaf(alpha, tv.w - hv.w, hv.w);
                const float xpx = pv.x - mx, xpy = pv.y - my, xpz = pv.z - mz, xpw = pv.w - mw;
                const float xnx = nv.x - mx, xny = nv.y - my, xnz = nv.z - mz, xnw = nv.w - mw;
                acc = fmaf(xnx, xnx, acc); acc = fmaf(-xpx, xpx, acc);
                acc = fmaf(xny, xny, acc); acc = fmaf(-xpy, xpy, acc);
                acc = fmaf(xnz, xnz, acc); acc = fmaf(-xpz, xpz, acc);
                acc = fmaf(xnw, xnw, acc); acc = fmaf(-xpw, xpw, acc);
            }
        }

        // warp tree reduce
#pragma unroll
        for (int off = 16; off; off >>= 1)
            acc += __shfl_xor_sync(0xffffffffu, acc, off);

        const float cur = fmaf(acc, inv, BETA_F);
        if (cur > 0.0f) wloss += cur;
    }

    __shared__ float sm[WARPS];
    __shared__ bool  amLast;
    if (lane == 0) sm[warp] = wloss;
    __syncthreads();
    if (threadIdx.x == 0) {
        float t = 0.0f;
#pragma unroll
        for (int w = 0; w < WARPS; w++) t += sm[w];
        g_partials[blockIdx.x] = t;
        __threadfence();
        // wraps to 0 when old == NBLOCKS-1 -> self-resetting for graph replay
        unsigned old = atomicInc(&g_ctr, NBLOCKS - 1);
        amLast = (old == NBLOCKS - 1);
    }
    __syncthreads();

    if (amLast) {
        // Deterministic final reduction: fixed tree order over g_partials.
        __shared__ float fin[NTHREADS];
        float t = 0.0f;
#pragma unroll
        for (int k = 0; k < NBLOCKS / NTHREADS; k++)
            t += g_partials[threadIdx.x + k * NTHREADS];
        fin[threadIdx.x] = t;
        __syncthreads();
#pragma unroll
        for (int st = NTHREADS / 2; st > 0; st >>= 1) {
            if ((int)threadIdx.x < st) fin[threadIdx.x] += fin[threadIdx.x + st];
            __syncthreads();
        }
        if (threadIdx.x == 0) out[0] = fin[0] / (float)BB;
    }
}

extern "C" void kernel_launch(void* const* d_in, const int* in_sizes, int n_in,
                              void* d_out, int out_size)
{
    const float* bridges = (const float*)d_in[0];
    const int*   b_inx   = (const int*)  d_in[1];
    const int*   neg_i   = (const int*)  d_in[2];
    const int*   neg_j   = (const int*)  d_in[3];

    bridge_loss_fused<<<NBLOCKS, NTHREADS>>>(bridges, b_inx, neg_i, neg_j,
                                             (float*)d_out);
}